// round 17
// baseline (speedup 1.0000x reference)
#include <cuda_runtime.h>
#include <cuda_bf16.h>
#include <math.h>

// ---------------------------------------------------------------------------
// SINGLE-KERNEL fused pipeline (persistent grid + device grid barriers).
// 3x exact top-K over columns of A (N x 2), (value desc, index asc) = lax.top_k.
// 296 blocks x 256 threads; THREE grid barriers, ONE pass over A:
//   P1 hist      : 16384-bin histograms of fkey(v), fkey(vo); A in regs;
//                  g_nwork reset (block 0)
//   P2 base      : 128 blocks; warp-shuffle scans; writes g_base offset tables,
//                  worklist of (bin, sub) entries with SUB=32 keys each
//   P3 compact   : scatter candidates (A from REGISTERS) via atomicAdd(g_base);
//                  also zeroes g_hist (dead after P2) for the next replay
//   P4 rank+gemv : one block per worklist entry: warp 0 ranks the entry's <=32
//                  keys against its segment (keys unique => exact position),
//                  then 8 warps gemv 4 rows each (single trip) + softmax.
//                  No g_idx array, no barrier between rank and gemv.
// State zero at module load; each call re-zeroes => every call identical.
// Output (float32, 15K): [0,3K) labels | [3K,9K) logits | [9K,15K) softmax
// ---------------------------------------------------------------------------

#define NBINS   16384
#define SHIFT   18
#define NCHUNK  128
#define CH      128                // bins per chunk
#define SUB     32                 // keys per worklist entry (= rows gemv'd)
#define CAP     4096
#define KMAX    2048
#define SEGB    1024
#define WLCAP   8192
#define BLKS    296
#define THR     256

__device__ unsigned            g_hist[2][NBINS];
__device__ int                 g_base[3][NBINS];
__device__ unsigned            g_bin[3];            // lo0 (>=), hi1 (<=), lo2 (>=)
__device__ int                 g_nwork;
__device__ int4                g_work[WLCAP];       // {sel|sub<<2, bin, start, cnt}
__device__ unsigned long long  g_scat[3][CAP];
__device__ unsigned            g_arrive;
__device__ volatile unsigned   g_gen;

__device__ __forceinline__ unsigned fkey(float f) {
    unsigned u = __float_as_uint(f);
    return (u & 0x80000000u) ? ~u : (u | 0x80000000u);   // monotonic
}

// Generation-counter grid barrier. Safe: 296 blocks, >=304 resident slots
// at __launch_bounds__(256, 2) on 152 SMs.
__device__ __forceinline__ void grid_sync() {
    __syncthreads();
    if (threadIdx.x == 0) {
        unsigned gen = g_gen;
        __threadfence();                               // release
        if (atomicAdd(&g_arrive, 1u) == (unsigned)BLKS - 1u) {
            g_arrive = 0u;
            __threadfence();
            g_gen = gen + 1u;
        } else {
            while (g_gen == gen) __nanosleep(32);
            __threadfence();                           // acquire
        }
    }
    __syncthreads();
}

__global__ __launch_bounds__(THR, 2)
void fused_kernel(const float* __restrict__ h, const float4* __restrict__ A4,
                  const float* __restrict__ W, const float* __restrict__ bvec,
                  const int* __restrict__ bag, float* __restrict__ out,
                  int N, int D, int K) {
    __shared__ unsigned long long s_u64[SEGB];        // 8KB: keys / P2 scratch
    __shared__ float s_w[1024];                       // 4KB: W cols (D<=512)
    __shared__ int   s_pos[SUB];
    __shared__ int   s_idx[SUB];
    unsigned* s_u32 = (unsigned*)s_u64;

    const int tid = threadIdx.x;
    const int bid = blockIdx.x;
    const int bg  = __ldg(bag);
    const unsigned uK = (unsigned)K;
    const int N2 = N >> 1;
    const int gsz = BLKS * THR;
    const int i0 = bid * THR + tid;

    // ---- P1: histograms; keep this thread's float4; reset g_nwork --------------
    if (bid == 0 && tid == 0) g_nwork = 0;
    float4 areg = make_float4(0.f, 0.f, 0.f, 0.f);
    if (i0 < N2) areg = A4[i0];
    for (int i = i0; i < N2; i += gsz) {
        float4 a = (i == i0) ? areg : A4[i];
        float v0  = bg ? a.y : a.x,  vo0 = bg ? a.x : a.y;
        float v1  = bg ? a.w : a.z,  vo1 = bg ? a.z : a.w;
        atomicAdd(&g_hist[0][fkey(v0)  >> SHIFT], 1u);
        atomicAdd(&g_hist[1][fkey(vo0) >> SHIFT], 1u);
        atomicAdd(&g_hist[0][fkey(v1)  >> SHIFT], 1u);
        atomicAdd(&g_hist[1][fkey(vo1) >> SHIFT], 1u);
    }
    if ((N & 1) && bid == 0 && tid == 0) {
        const float2* A2 = (const float2*)A4;
        float2 a = A2[N - 1];
        atomicAdd(&g_hist[0][fkey(bg ? a.y : a.x) >> SHIFT], 1u);
        atomicAdd(&g_hist[1][fkey(bg ? a.x : a.y) >> SHIFT], 1u);
    }
    grid_sync();

    // ---- P2: shuffle-scan offset tables + worklist (blocks < NCHUNK) -----------
    if (bid < NCHUNK) {
        const int lane = tid & 31;
        #pragma unroll
        for (int hh = 0; hh < 2; hh++) {
            // 1) per-thread partial: sum 64 consecutive bins (16 uint4 loads)
            {
                const uint4* h4 = (const uint4*)g_hist[hh];
                unsigned sum = 0;
                #pragma unroll
                for (int q = 0; q < 16; q++) {
                    uint4 c = h4[tid * 16 + q];
                    sum += c.x + c.y + c.z + c.w;
                }
                s_u32[tid] = sum;       // thread t covers bins [64t, 64t+64)
            }
            __syncthreads();
            // 2) warp 0: chunk sums (4 chunks/lane) + inclusive shuffle scan
            if (tid < 32) {
                unsigned c0 = s_u32[8 * tid + 0] + s_u32[8 * tid + 1];
                unsigned c1 = s_u32[8 * tid + 2] + s_u32[8 * tid + 3];
                unsigned c2 = s_u32[8 * tid + 4] + s_u32[8 * tid + 5];
                unsigned c3 = s_u32[8 * tid + 6] + s_u32[8 * tid + 7];
                unsigned p0 = c0, p1 = p0 + c1, p2 = p1 + c2, p3 = p2 + c3;
                unsigned inc = p3;
                #pragma unroll
                for (int o = 1; o < 32; o <<= 1) {
                    unsigned v = __shfl_up_sync(0xFFFFFFFFu, inc, o);
                    if (tid >= o) inc += v;
                }
                unsigned excl = inc - p3;
                s_u32[256 + 4 * tid + 0] = p0 + excl;
                s_u32[256 + 4 * tid + 1] = p1 + excl;
                s_u32[256 + 4 * tid + 2] = p2 + excl;
                s_u32[256 + 4 * tid + 3] = p3 + excl;
            }
            __syncthreads();
            const unsigned total = s_u32[256 + NCHUNK - 1];
            const unsigned csum_bid = s_u32[2 * bid] + s_u32[2 * bid + 1];
            const unsigned choff = s_u32[256 + bid] - csum_bid;

            // 3) bin scan: threads<128 (warps 0-3), shuffle scan + warp offsets
            unsigned cnt = 0, incl = 0;
            if (tid < CH) {
                cnt = g_hist[hh][bid * CH + tid];
                unsigned v = cnt;
                #pragma unroll
                for (int o = 1; o < 32; o <<= 1) {
                    unsigned w = __shfl_up_sync(0xFFFFFFFFu, v, o);
                    if (lane >= o) v += w;
                }
                if (lane == 31) s_u32[384 + (tid >> 5)] = v;  // 4 warp totals
                incl = v;
            }
            __syncthreads();
            if (tid < CH) {
                unsigned woff = 0;
                #pragma unroll
                for (int w = 0; w < 3; w++)
                    if (w < (tid >> 5)) woff += s_u32[384 + w];
                incl += woff + choff;

                const int b = bid * CH + tid;
                // top-K (sel0 from hist0, sel2 from hist1)
                const int selt = hh ? 2 : 0;
                const unsigned above = total - incl;
                g_base[selt][b] = (int)above;
                if (above < uK && cnt > 0) {
                    if (above + cnt >= uK) g_bin[selt] = (unsigned)b;
                    for (int sub = 0; sub * SUB < (int)cnt; sub++) {
                        int w = atomicAdd(&g_nwork, 1);
                        if (w < WLCAP)
                            g_work[w] = make_int4(selt | (sub << 2), b, (int)above, (int)cnt);
                    }
                }
                // bottom-K (hist0 -> sel1)
                if (hh == 0) {
                    const unsigned below = incl - cnt;
                    g_base[1][b] = (int)below;
                    if (below < uK && cnt > 0) {
                        if (below + cnt >= uK) g_bin[1] = (unsigned)b;
                        for (int sub = 0; sub * SUB < (int)cnt; sub++) {
                            int w = atomicAdd(&g_nwork, 1);
                            if (w < WLCAP)
                                g_work[w] = make_int4(1 | (sub << 2), b, (int)below, (int)cnt);
                        }
                    }
                }
            }
            __syncthreads();
        }
    }
    grid_sync();

    // ---- P3: compact/scatter from REGISTERS; zero g_hist (dead after P2) -------
    {
        const unsigned lo0 = g_bin[0], hi1 = g_bin[1], lo2 = g_bin[2];
        for (int i = i0; i < N2; i += gsz) {
            float4 a = (i == i0) ? areg : A4[i];
            #pragma unroll
            for (int e = 0; e < 2; e++) {
                float v  = e ? (bg ? a.w : a.z) : (bg ? a.y : a.x);
                float vo = e ? (bg ? a.z : a.w) : (bg ? a.x : a.y);
                const int idx = i * 2 + e;
                unsigned k0 = fkey(v), k2 = fkey(vo);
                unsigned b0 = k0 >> SHIFT, b2 = k2 >> SHIFT;
                unsigned long long il = (unsigned)(~(unsigned)idx);
                if (b0 >= lo0) {
                    int p = atomicAdd(&g_base[0][b0], 1);
                    if (p < CAP) g_scat[0][p] = ((unsigned long long)k0 << 32) | il;
                }
                if (b0 <= hi1) {
                    int p = atomicAdd(&g_base[1][b0], 1);
                    if (p < CAP) g_scat[1][p] = ((unsigned long long)(~k0) << 32) | il;
                }
                if (b2 >= lo2) {
                    int p = atomicAdd(&g_base[2][b2], 1);
                    if (p < CAP) g_scat[2][p] = ((unsigned long long)k2 << 32) | il;
                }
            }
        }
        if ((N & 1) && bid == 0 && tid == 0) {
            const float2* A2 = (const float2*)A4;
            float2 a = A2[N - 1];
            float v = bg ? a.y : a.x, vo = bg ? a.x : a.y;
            unsigned k0 = fkey(v), k2 = fkey(vo);
            unsigned b0 = k0 >> SHIFT, b2 = k2 >> SHIFT;
            unsigned long long il = (unsigned)(~(unsigned)(N - 1));
            if (b0 >= lo0) {
                int p = atomicAdd(&g_base[0][b0], 1);
                if (p < CAP) g_scat[0][p] = ((unsigned long long)k0 << 32) | il;
            }
            if (b0 <= hi1) {
                int p = atomicAdd(&g_base[1][b0], 1);
                if (p < CAP) g_scat[1][p] = ((unsigned long long)(~k0) << 32) | il;
            }
            if (b2 >= lo2) {
                int p = atomicAdd(&g_base[2][b2], 1);
                if (p < CAP) g_scat[2][p] = ((unsigned long long)k2 << 32) | il;
            }
        }
        // zero histograms for the next graph replay (read only in P2)
        uint4* hp = (uint4*)g_hist;
        const int totalw = 2 * NBINS / 4;
        for (int i = bid * THR + tid; i < totalw; i += gsz)
            hp[i] = make_uint4(0u, 0u, 0u, 0u);
    }
    grid_sync();

    // ---- P4: rank + gemv + softmax, one worklist entry per block ---------------
    {
        // stage W columns in smem (conflict-free float4 reads)
        for (int j = tid; j < D; j += THR) {
            s_w[j]     = W[j * 2 + 0];
            s_w[D + j] = W[j * 2 + 1];
        }
        __syncthreads();
        const float4* w04 = (const float4*)s_w;
        const float4* w14 = (const float4*)(s_w + D);

        const int warp = tid >> 5, lane = tid & 31;
        const int nq = D >> 2;
        const float bb0 = bvec[0], bb1 = bvec[1];
        const int nwork = g_nwork < WLCAP ? g_nwork : WLCAP;

        for (int e = bid; e < nwork; e += BLKS) {
            int4 w = g_work[e];
            const int sel = w.x & 3, sub = w.x >> 2;
            const int start = w.z;
            int cnt = w.w;
            if (start + cnt > CAP) cnt = CAP - start;
            if (cnt > SEGB) cnt = SEGB;
            const int lo = sub * SUB;
            int hi = lo + SUB; if (hi > cnt) hi = cnt;
            if (lo >= cnt) continue;

            for (int j = tid; j < cnt; j += THR) s_u64[j] = g_scat[sel][start + j];
            __syncthreads();

            // warp 0: rank my 32 keys against the whole segment
            if (tid < SUB) {
                int pos = -1, idx = 0;
                if (lo + tid < hi) {
                    unsigned long long key = s_u64[lo + tid];
                    int rank = 0;
                    int j = 0;
                    #pragma unroll 4
                    for (; j + 3 < cnt; j += 4) {
                        rank += (s_u64[j]     > key);
                        rank += (s_u64[j + 1] > key);
                        rank += (s_u64[j + 2] > key);
                        rank += (s_u64[j + 3] > key);
                    }
                    for (; j < cnt; j++) rank += (s_u64[j] > key);
                    int p = start + rank;
                    if (p < K) pos = p;
                    idx = (int)(~(unsigned)(key & 0xFFFFFFFFull));
                }
                s_pos[tid] = pos;
                s_idx[tid] = idx;
            }
            __syncthreads();

            // 8 warps x 4 rows, single trip
            const int kb = warp * 4;
            const int q0p = s_pos[kb + 0], q1p = s_pos[kb + 1];
            const int q2p = s_pos[kb + 2], q3p = s_pos[kb + 3];
            const bool any = (q0p >= 0) | (q1p >= 0) | (q2p >= 0) | (q3p >= 0);
            if (any) {
                const int i0r = (q0p >= 0) ? s_idx[kb + 0] : 0;
                const int i1r = (q1p >= 0) ? s_idx[kb + 1] : i0r;
                const int i2r = (q2p >= 0) ? s_idx[kb + 2] : i0r;
                const int i3r = (q3p >= 0) ? s_idx[kb + 3] : i0r;
                const float4* p0 = (const float4*)(h + (size_t)i0r * D);
                const float4* p1 = (const float4*)(h + (size_t)i1r * D);
                const float4* p2 = (const float4*)(h + (size_t)i2r * D);
                const float4* p3 = (const float4*)(h + (size_t)i3r * D);

                float c00 = 0.f, c01 = 0.f, c10 = 0.f, c11 = 0.f;
                float c20 = 0.f, c21 = 0.f, c30 = 0.f, c31 = 0.f;

                int t = lane;
                for (; t + 32 < nq; t += 64) {
                    float4 a0 = p0[t],      a1 = p1[t],      a2 = p2[t],      a3 = p3[t];
                    float4 d0 = p0[t + 32], d1 = p1[t + 32], d2 = p2[t + 32], d3 = p3[t + 32];
                    float4 w0 = w04[t],      w1 = w14[t];
                    float4 e0 = w04[t + 32], e1 = w14[t + 32];
                    c00 = fmaf(a0.x, w0.x, c00); c01 = fmaf(a0.x, w1.x, c01);
                    c10 = fmaf(a1.x, w0.x, c10); c11 = fmaf(a1.x, w1.x, c11);
                    c20 = fmaf(a2.x, w0.x, c20); c21 = fmaf(a2.x, w1.x, c21);
                    c30 = fmaf(a3.x, w0.x, c30); c31 = fmaf(a3.x, w1.x, c31);
                    c00 = fmaf(a0.y, w0.y, c00); c01 = fmaf(a0.y, w1.y, c01);
                    c10 = fmaf(a1.y, w0.y, c10); c11 = fmaf(a1.y, w1.y, c11);
                    c20 = fmaf(a2.y, w0.y, c20); c21 = fmaf(a2.y, w1.y, c21);
                    c30 = fmaf(a3.y, w0.y, c30); c31 = fmaf(a3.y, w1.y, c31);
                    c00 = fmaf(a0.z, w0.z, c00); c01 = fmaf(a0.z, w1.z, c01);
                    c10 = fmaf(a1.z, w0.z, c10); c11 = fmaf(a1.z, w1.z, c11);
                    c20 = fmaf(a2.z, w0.z, c20); c21 = fmaf(a2.z, w1.z, c21);
                    c30 = fmaf(a3.z, w0.z, c30); c31 = fmaf(a3.z, w1.z, c31);
                    c00 = fmaf(a0.w, w0.w, c00); c01 = fmaf(a0.w, w1.w, c01);
                    c10 = fmaf(a1.w, w0.w, c10); c11 = fmaf(a1.w, w1.w, c11);
                    c20 = fmaf(a2.w, w0.w, c20); c21 = fmaf(a2.w, w1.w, c21);
                    c30 = fmaf(a3.w, w0.w, c30); c31 = fmaf(a3.w, w1.w, c31);
                    c00 = fmaf(d0.x, e0.x, c00); c01 = fmaf(d0.x, e1.x, c01);
                    c10 = fmaf(d1.x, e0.x, c10); c11 = fmaf(d1.x, e1.x, c11);
                    c20 = fmaf(d2.x, e0.x, c20); c21 = fmaf(d2.x, e1.x, c21);
                    c30 = fmaf(d3.x, e0.x, c30); c31 = fmaf(d3.x, e1.x, c31);
                    c00 = fmaf(d0.y, e0.y, c00); c01 = fmaf(d0.y, e1.y, c01);
                    c10 = fmaf(d1.y, e0.y, c10); c11 = fmaf(d1.y, e1.y, c11);
                    c20 = fmaf(d2.y, e0.y, c20); c21 = fmaf(d2.y, e1.y, c21);
                    c30 = fmaf(d3.y, e0.y, c30); c31 = fmaf(d3.y, e1.y, c31);
                    c00 = fmaf(d0.z, e0.z, c00); c01 = fmaf(d0.z, e1.z, c01);
                    c10 = fmaf(d1.z, e0.z, c10); c11 = fmaf(d1.z, e1.z, c11);
                    c20 = fmaf(d2.z, e0.z, c20); c21 = fmaf(d2.z, e1.z, c21);
                    c30 = fmaf(d3.z, e0.z, c30); c31 = fmaf(d3.z, e1.z, c31);
                    c00 = fmaf(d0.w, e0.w, c00); c01 = fmaf(d0.w, e1.w, c01);
                    c10 = fmaf(d1.w, e0.w, c10); c11 = fmaf(d1.w, e1.w, c11);
                    c20 = fmaf(d2.w, e0.w, c20); c21 = fmaf(d2.w, e1.w, c21);
                    c30 = fmaf(d3.w, e0.w, c30); c31 = fmaf(d3.w, e1.w, c31);
                }
                for (; t < nq; t += 32) {
                    float4 a0 = p0[t], a1 = p1[t], a2 = p2[t], a3 = p3[t];
                    float4 w0 = w04[t], w1 = w14[t];
                    c00 = fmaf(a0.x, w0.x, c00); c01 = fmaf(a0.x, w1.x, c01);
                    c10 = fmaf(a1.x, w0.x, c10); c11 = fmaf(a1.x, w1.x, c11);
                    c20 = fmaf(a2.x, w0.x, c20); c21 = fmaf(a2.x, w1.x, c21);
                    c30 = fmaf(a3.x, w0.x, c30); c31 = fmaf(a3.x, w1.x, c31);
                    c00 = fmaf(a0.y, w0.y, c00); c01 = fmaf(a0.y, w1.y, c01);
                    c10 = fmaf(a1.y, w0.y, c10); c11 = fmaf(a1.y, w1.y, c11);
                    c20 = fmaf(a2.y, w0.y, c20); c21 = fmaf(a2.y, w1.y, c21);
                    c30 = fmaf(a3.y, w0.y, c30); c31 = fmaf(a3.y, w1.y, c31);
                    c00 = fmaf(a0.z, w0.z, c00); c01 = fmaf(a0.z, w1.z, c01);
                    c10 = fmaf(a1.z, w0.z, c10); c11 = fmaf(a1.z, w1.z, c11);
                    c20 = fmaf(a2.z, w0.z, c20); c21 = fmaf(a2.z, w1.z, c21);
                    c30 = fmaf(a3.z, w0.z, c30); c31 = fmaf(a3.z, w1.z, c31);
                    c00 = fmaf(a0.w, w0.w, c00); c01 = fmaf(a0.w, w1.w, c01);
                    c10 = fmaf(a1.w, w0.w, c10); c11 = fmaf(a1.w, w1.w, c11);
                    c20 = fmaf(a2.w, w0.w, c20); c21 = fmaf(a2.w, w1.w, c21);
                    c30 = fmaf(a3.w, w0.w, c30); c31 = fmaf(a3.w, w1.w, c31);
                }

                #pragma unroll
                for (int o = 16; o; o >>= 1) {
                    c00 += __shfl_down_sync(0xFFFFFFFFu, c00, o);
                    c01 += __shfl_down_sync(0xFFFFFFFFu, c01, o);
                    c10 += __shfl_down_sync(0xFFFFFFFFu, c10, o);
                    c11 += __shfl_down_sync(0xFFFFFFFFu, c11, o);
                    c20 += __shfl_down_sync(0xFFFFFFFFu, c20, o);
                    c21 += __shfl_down_sync(0xFFFFFFFFu, c21, o);
                    c30 += __shfl_down_sync(0xFFFFFFFFu, c30, o);
                    c31 += __shfl_down_sync(0xFFFFFFFFu, c31, o);
                }

                if (lane == 0) {
                    float z0s[4] = {c00, c10, c20, c30};
                    float z1s[4] = {c01, c11, c21, c31};
                    int   ps[4]  = {q0p, q1p, q2p, q3p};
                    const float lab = (sel == 0) ? 1.0f : 0.0f;
                    #pragma unroll
                    for (int q = 0; q < 4; q++) {
                        if (ps[q] < 0) continue;
                        int r = sel * K + ps[q];
                        float z0 = z0s[q] + bb0, z1 = z1s[q] + bb1;
                        float m = fmaxf(z0, z1);
                        float e0 = expf(z0 - m), e1 = expf(z1 - m);
                        float inv = 1.0f / (e0 + e1);
                        out[r] = lab;
                        out[3 * K + r * 2 + 0] = z0;
                        out[3 * K + r * 2 + 1] = z1;
                        out[9 * K + r * 2 + 0] = e0 * inv;
                        out[9 * K + r * 2 + 1] = e1 * inv;
                    }
                }
            }
            __syncthreads();   // protect s_u64/s_pos/s_idx before next entry
        }
    }
}

extern "C" void kernel_launch(void* const* d_in, const int* in_sizes, int n_in,
                              void* d_out, int out_size) {
    const float* h = (const float*)d_in[0];   // (N,1,D)
    const float* A = (const float*)d_in[1];   // (N,1,2)
    const float* W = (const float*)d_in[2];   // (D,2)
    const float* b = (const float*)d_in[3];   // (2,)
    const int* bag = (const int*)d_in[4];

    const int N = in_sizes[1] / 2;
    const int D = in_sizes[0] / N;
    int K = (int)(0.02 * (double)N);
    if (K == 0) K = 8;
    if (K > KMAX) K = KMAX;

    fused_kernel<<<BLKS, THR>>>(h, (const float4*)A, W, b, bag,
                                (float*)d_out, N, D, K);
}